// round 16
// baseline (speedup 1.0000x reference)
#include <cuda_runtime.h>
#include <cuda_fp16.h>
#include <stdint.h>

// ---------------- scratch (alloc-free: __device__ globals) ----------------
__device__ __half g_S [16u * 1024u * 2048u];   // exp(logits), unnormalized  [B,NQ,NK] fp16
__device__ __half g_Vt[16u * 256u  * 2048u];   // V'^T = W @ V^T  [B,O,NK]   fp16
__device__ float  g_rsum[16u * 1024u];         // per-row sum of exp(logits)

// ---------------- helpers ----------------
__device__ __forceinline__ uint32_t smem_u32(const void* p) {
    uint32_t a;
    asm("{ .reg .u64 t; cvta.to.shared.u64 t, %1; cvt.u32.u64 %0, t; }" : "=r"(a) : "l"(p));
    return a;
}
__device__ __forceinline__ uint32_t f16x2(float lo, float hi) {
    uint32_t u;
    asm("cvt.rn.f16x2.f32 %0, %1, %2;" : "=r"(u) : "f"(hi), "f"(lo));
    return u;
}
__device__ __forceinline__ void mma_f16(float c[4], const uint32_t a[4], const uint32_t b[2]) {
    asm volatile(
        "mma.sync.aligned.m16n8k16.row.col.f32.f16.f16.f32 "
        "{%0,%1,%2,%3}, {%4,%5,%6,%7}, {%8,%9}, {%0,%1,%2,%3};"
        : "+f"(c[0]), "+f"(c[1]), "+f"(c[2]), "+f"(c[3])
        : "r"(a[0]), "r"(a[1]), "r"(a[2]), "r"(a[3]), "r"(b[0]), "r"(b[1]));
}
__device__ __forceinline__ void ldsm4(uint32_t& r0, uint32_t& r1, uint32_t& r2, uint32_t& r3,
                                      uint32_t addr) {
    asm volatile("ldmatrix.sync.aligned.m8n8.x4.shared.b16 {%0,%1,%2,%3}, [%4];"
                 : "=r"(r0), "=r"(r1), "=r"(r2), "=r"(r3) : "r"(addr));
}
__device__ __forceinline__ void sts64(uint32_t a, uint32_t x, uint32_t y) {
    asm volatile("st.shared.v2.b32 [%0], {%1,%2};" :: "r"(a), "r"(x), "r"(y) : "memory");
}
__device__ __forceinline__ void sts128(uint32_t a, uint4 v) {
    asm volatile("st.shared.v4.b32 [%0], {%1,%2,%3,%4};"
                 :: "r"(a), "r"(v.x), "r"(v.y), "r"(v.z), "r"(v.w) : "memory");
}

// ---------------- tiling ----------------
// CTA tile 128x128x32, 4 warps as 2(M) x 2(N), warp tile 64x64. 128 threads.
// Two CTAs/SM. fp16 smem rows: 64B data, stride 80B (conflict-free ldmatrix).
constexpr int BM = 128, BN = 128, BK = 32;
constexpr int SBH   = 80;                   // bytes per smem row
constexpr int A_B   = BM * SBH;             // 10240
constexpr int STG_B = (BM + BN) * SBH;      // 20480 per stage
constexpr int SMEM_DB = 2 * STG_B;          // 40960 (double-buffered)

// ===================== zero row_sum =====================
__global__ __launch_bounds__(256)
void zero_rs(float4* __restrict__ rs4)
{
    rs4[blockIdx.x * 256 + threadIdx.x] = make_float4(0.f, 0.f, 0.f, 0.f);
}

// ===================== K1: fp32 inputs (in-kernel cvt), fused epilogue =====
// P[z][m][n] = exp(scale * sum_k Q[z][m][k]*Kk[z][n][k])  (mask==0 -> 0), fp16.
// Row sums of P accumulate into rsum via atomics.
__global__ __launch_bounds__(128, 2)
void gemm_k1(const float* __restrict__ Ag, const float* __restrict__ Bg,
             __half* __restrict__ Cg, int N, int K,
             long long sA, long long sB, long long sC,
             const int* __restrict__ maskg, long long sMask,
             float* __restrict__ rsum, float scale)
{
    extern __shared__ char smem[];

    const int tid  = threadIdx.x;
    const int lane = tid & 31;
    const int warp = tid >> 5;
    const int wm = (warp & 1) * 64;
    const int wn = (warp >> 1) * 64;
    const int z  = blockIdx.z;
    const int m0 = blockIdx.y * BM;
    const int n0 = blockIdx.x * BN;

    const float* A = Ag + (size_t)z * sA;
    const float* B = Bg + (size_t)z * sB;

    const uint32_t sbase = smem_u32(smem);
    const uint32_t aRowB = (uint32_t)(wm + (lane & 15)) * SBH + (uint32_t)(lane >> 4) * 16;
    const uint32_t bRowB = (uint32_t)(wn + (lane & 7) + ((lane >> 4) << 3)) * SBH
                         + (uint32_t)((lane >> 3) & 1) * 16;
    const int KT = K / BK;

    float4 ra[8], rb[8];
    auto load_regs = [&](int c) {
        const int koff = c * BK;
#pragma unroll
        for (int i = 0; i < 8; i++) {
            int f = tid + 128 * i, r = f >> 3, q = (f & 7) * 4;
            ra[i] = *(const float4*)(A + (size_t)(m0 + r) * K + koff + q);
        }
#pragma unroll
        for (int i = 0; i < 8; i++) {
            int f = tid + 128 * i, r = f >> 3, q = (f & 7) * 4;
            rb[i] = *(const float4*)(B + (size_t)(n0 + r) * K + koff + q);
        }
    };
    auto store_stage = [&](int s) {
        const uint32_t st = sbase + (uint32_t)s * STG_B;
#pragma unroll
        for (int i = 0; i < 8; i++) {
            int f = tid + 128 * i, r = f >> 3, q = (f & 7) * 4;
            sts64(st + (uint32_t)r * SBH + (uint32_t)q * 2,
                  f16x2(ra[i].x, ra[i].y), f16x2(ra[i].z, ra[i].w));
        }
#pragma unroll
        for (int i = 0; i < 8; i++) {
            int f = tid + 128 * i, r = f >> 3, q = (f & 7) * 4;
            sts64(st + (uint32_t)A_B + (uint32_t)r * SBH + (uint32_t)q * 2,
                  f16x2(rb[i].x, rb[i].y), f16x2(rb[i].z, rb[i].w));
        }
    };

    float acc[4][8][4];
#pragma unroll
    for (int i = 0; i < 4; i++)
#pragma unroll
        for (int j = 0; j < 8; j++)
#pragma unroll
            for (int r = 0; r < 4; r++) acc[i][j][r] = 0.0f;

    load_regs(0);
    store_stage(0);
    __syncthreads();
    if (KT > 1) load_regs(1);

    for (int kb = 0; kb < KT; ++kb) {
        const int cur = kb & 1;
        if (kb + 1 < KT) store_stage(cur ^ 1);
        if (kb + 2 < KT) load_regs(kb + 2);

        const uint32_t curBase = sbase + (uint32_t)cur * STG_B;
        const uint32_t aB = curBase + aRowB;
        const uint32_t bB = curBase + (uint32_t)A_B + bRowB;

#pragma unroll
        for (int ks = 0; ks < 2; ++ks) {
            const uint32_t kB = (uint32_t)ks * 32;
            uint32_t af[4][4], bf[8][2];
#pragma unroll
            for (int mi = 0; mi < 4; mi++)
                ldsm4(af[mi][0], af[mi][1], af[mi][2], af[mi][3],
                      aB + (uint32_t)mi * (16 * SBH) + kB);
#pragma unroll
            for (int pr = 0; pr < 4; pr++)
                ldsm4(bf[2 * pr][0], bf[2 * pr][1], bf[2 * pr + 1][0], bf[2 * pr + 1][1],
                      bB + (uint32_t)pr * (16 * SBH) + kB);
#pragma unroll
            for (int mi = 0; mi < 4; mi++)
#pragma unroll
                for (int ni = 0; ni < 8; ni++)
                    mma_f16(acc[mi][ni], af[mi], bf[ni]);
        }
        __syncthreads();
    }

    // ---- fused epilogue: exp + mask -> store P, reduce row partial sums ----
    __half* C = Cg + (size_t)z * sC;
    const int* Mk = maskg + (size_t)z * sMask;
    float* RS = rsum + (size_t)z * 1024;

#pragma unroll
    for (int mi = 0; mi < 4; mi++) {
        const int row0 = m0 + wm + mi * 16 + (lane >> 2);
        float psum[2] = {0.0f, 0.0f};
#pragma unroll
        for (int ni = 0; ni < 8; ni++) {
            const int col = n0 + wn + ni * 8 + (lane & 3) * 2;
#pragma unroll
            for (int h = 0; h < 2; ++h) {
                const int row = row0 + h * 8;
                int2 mk = *(const int2*)(Mk + (size_t)row * N + col);
                float v0 = mk.x ? __expf(acc[mi][ni][2 * h] * scale)     : 0.0f;
                float v1 = mk.y ? __expf(acc[mi][ni][2 * h + 1] * scale) : 0.0f;
                psum[h] += v0 + v1;
                *(__half2*)(C + (size_t)row * N + col) = __floats2half2_rn(v0, v1);
            }
        }
#pragma unroll
        for (int h = 0; h < 2; ++h) {
            float s = psum[h];
            s += __shfl_xor_sync(0xffffffffu, s, 1);
            s += __shfl_xor_sync(0xffffffffu, s, 2);
            if ((lane & 3) == 0) atomicAdd(RS + row0 + h * 8, s);
        }
    }
}

// ===================== K3: fp16 in -> fp32 out, scale by 1/rowsum + bias ===
__global__ __launch_bounds__(128, 2)
void gemm_h16(const __half* __restrict__ Ag, const __half* __restrict__ Bg,
              float* __restrict__ Cg, int N, int K,
              long long sA, long long sB, long long sC,
              const float* __restrict__ bias, const float* __restrict__ rsum)
{
    extern __shared__ char smem[];

    const int tid  = threadIdx.x;
    const int lane = tid & 31;
    const int warp = tid >> 5;
    const int wm = (warp & 1) * 64;
    const int wn = (warp >> 1) * 64;
    const int z  = blockIdx.z;
    const int m0 = blockIdx.y * BM;
    const int n0 = blockIdx.x * BN;

    const __half* A = Ag + (size_t)z * sA;
    const __half* B = Bg + (size_t)z * sB;

    const uint32_t sbase = smem_u32(smem);
    const uint32_t aRowB = (uint32_t)(wm + (lane & 15)) * SBH + (uint32_t)(lane >> 4) * 16;
    const uint32_t bRowB = (uint32_t)(wn + (lane & 7) + ((lane >> 4) << 3)) * SBH
                         + (uint32_t)((lane >> 3) & 1) * 16;
    const int KT = K / BK;

    uint4 ra[4], rb[4];
    auto load_regs = [&](int c) {
        const int koff = c * BK;
#pragma unroll
        for (int i = 0; i < 4; i++) {
            int f = tid + 128 * i, r = f >> 2, sg = f & 3;
            ra[i] = *(const uint4*)(A + (size_t)(m0 + r) * K + koff + sg * 8);
        }
#pragma unroll
        for (int i = 0; i < 4; i++) {
            int f = tid + 128 * i, r = f >> 2, sg = f & 3;
            rb[i] = *(const uint4*)(B + (size_t)(n0 + r) * K + koff + sg * 8);
        }
    };
    auto store_stage = [&](int s) {
        const uint32_t st = sbase + (uint32_t)s * STG_B;
#pragma unroll
        for (int i = 0; i < 4; i++) {
            int f = tid + 128 * i, r = f >> 2, sg = f & 3;
            sts128(st + (uint32_t)r * SBH + (uint32_t)sg * 16, ra[i]);
        }
#pragma unroll
        for (int i = 0; i < 4; i++) {
            int f = tid + 128 * i, r = f >> 2, sg = f & 3;
            sts128(st + (uint32_t)A_B + (uint32_t)r * SBH + (uint32_t)sg * 16, rb[i]);
        }
    };

    float acc[4][8][4];
#pragma unroll
    for (int i = 0; i < 4; i++)
#pragma unroll
        for (int j = 0; j < 8; j++)
#pragma unroll
            for (int r = 0; r < 4; r++) acc[i][j][r] = 0.0f;

    load_regs(0);
    store_stage(0);
    __syncthreads();
    if (KT > 1) load_regs(1);

    for (int kb = 0; kb < KT; ++kb) {
        const int cur = kb & 1;
        if (kb + 1 < KT) store_stage(cur ^ 1);
        if (kb + 2 < KT) load_regs(kb + 2);

        const uint32_t curBase = sbase + (uint32_t)cur * STG_B;
        const uint32_t aB = curBase + aRowB;
        const uint32_t bB = curBase + (uint32_t)A_B + bRowB;

#pragma unroll
        for (int ks = 0; ks < 2; ++ks) {
            const uint32_t kB = (uint32_t)ks * 32;
            uint32_t af[4][4], bf[8][2];
#pragma unroll
            for (int mi = 0; mi < 4; mi++)
                ldsm4(af[mi][0], af[mi][1], af[mi][2], af[mi][3],
                      aB + (uint32_t)mi * (16 * SBH) + kB);
#pragma unroll
            for (int pr = 0; pr < 4; pr++)
                ldsm4(bf[2 * pr][0], bf[2 * pr][1], bf[2 * pr + 1][0], bf[2 * pr + 1][1],
                      bB + (uint32_t)pr * (16 * SBH) + kB);
#pragma unroll
            for (int mi = 0; mi < 4; mi++)
#pragma unroll
                for (int ni = 0; ni < 8; ni++)
                    mma_f16(acc[mi][ni], af[mi], bf[ni]);
        }
        __syncthreads();
    }

    float* C = Cg + (size_t)z * sC;
    const float* RS = rsum + (size_t)z * 1024;
#pragma unroll
    for (int mi = 0; mi < 4; mi++) {
        const int row0 = m0 + wm + mi * 16 + (lane >> 2);
        const float inv0 = 1.0f / RS[row0];
        const float inv1 = 1.0f / RS[row0 + 8];
#pragma unroll
        for (int ni = 0; ni < 8; ni++) {
            const int col = n0 + wn + ni * 8 + (lane & 3) * 2;
            const float b0 = bias[col], b1 = bias[col + 1];
            float2 o;
            o.x = acc[mi][ni][0] * inv0 + b0;
            o.y = acc[mi][ni][1] * inv0 + b1;
            *(float2*)(C + (size_t)row0 * N + col) = o;
            o.x = acc[mi][ni][2] * inv1 + b0;
            o.y = acc[mi][ni][3] * inv1 + b1;
            *(float2*)(C + (size_t)(row0 + 8) * N + col) = o;
        }
    }
}

// ===================== K0: fp32 inputs -> fp16 out =========================
__global__ __launch_bounds__(128, 2)
void gemm_a32(const float* __restrict__ Ag, const float* __restrict__ Bg,
              __half* __restrict__ Cg, int N, int K,
              long long sA, long long sB, long long sC)
{
    extern __shared__ char smem[];

    const int tid  = threadIdx.x;
    const int lane = tid & 31;
    const int warp = tid >> 5;
    const int wm = (warp & 1) * 64;
    const int wn = (warp >> 1) * 64;
    const int z  = blockIdx.z;
    const int m0 = blockIdx.y * BM;
    const int n0 = blockIdx.x * BN;

    const float* A = Ag + (size_t)z * sA;
    const float* B = Bg + (size_t)z * sB;

    const uint32_t sbase = smem_u32(smem);
    const uint32_t aRowB = (uint32_t)(wm + (lane & 15)) * SBH + (uint32_t)(lane >> 4) * 16;
    const uint32_t bRowB = (uint32_t)(wn + (lane & 7) + ((lane >> 4) << 3)) * SBH
                         + (uint32_t)((lane >> 3) & 1) * 16;
    const int KT = K / BK;

    float4 ra[8], rb[8];
    auto load_regs = [&](int c) {
        const int koff = c * BK;
#pragma unroll
        for (int i = 0; i < 8; i++) {
            int f = tid + 128 * i, r = f >> 3, q = (f & 7) * 4;
            ra[i] = *(const float4*)(A + (size_t)(m0 + r) * K + koff + q);
        }
#pragma unroll
        for (int i = 0; i < 8; i++) {
            int f = tid + 128 * i, r = f >> 3, q = (f & 7) * 4;
            rb[i] = *(const float4*)(B + (size_t)(n0 + r) * K + koff + q);
        }
    };
    auto store_stage = [&](int s) {
        const uint32_t st = sbase + (uint32_t)s * STG_B;
#pragma unroll
        for (int i = 0; i < 8; i++) {
            int f = tid + 128 * i, r = f >> 3, q = (f & 7) * 4;
            sts64(st + (uint32_t)r * SBH + (uint32_t)q * 2,
                  f16x2(ra[i].x, ra[i].y), f16x2(ra[i].z, ra[i].w));
        }
#pragma unroll
        for (int i = 0; i < 8; i++) {
            int f = tid + 128 * i, r = f >> 3, q = (f & 7) * 4;
            sts64(st + (uint32_t)A_B + (uint32_t)r * SBH + (uint32_t)q * 2,
                  f16x2(rb[i].x, rb[i].y), f16x2(rb[i].z, rb[i].w));
        }
    };

    float acc[4][8][4];
#pragma unroll
    for (int i = 0; i < 4; i++)
#pragma unroll
        for (int j = 0; j < 8; j++)
#pragma unroll
            for (int r = 0; r < 4; r++) acc[i][j][r] = 0.0f;

    load_regs(0);
    store_stage(0);
    __syncthreads();
    if (KT > 1) load_regs(1);

    for (int kb = 0; kb < KT; ++kb) {
        const int cur = kb & 1;
        if (kb + 1 < KT) store_stage(cur ^ 1);
        if (kb + 2 < KT) load_regs(kb + 2);

        const uint32_t curBase = sbase + (uint32_t)cur * STG_B;
        const uint32_t aB = curBase + aRowB;
        const uint32_t bB = curBase + (uint32_t)A_B + bRowB;

#pragma unroll
        for (int ks = 0; ks < 2; ++ks) {
            const uint32_t kB = (uint32_t)ks * 32;
            uint32_t af[4][4], bf[8][2];
#pragma unroll
            for (int mi = 0; mi < 4; mi++)
                ldsm4(af[mi][0], af[mi][1], af[mi][2], af[mi][3],
                      aB + (uint32_t)mi * (16 * SBH) + kB);
#pragma unroll
            for (int pr = 0; pr < 4; pr++)
                ldsm4(bf[2 * pr][0], bf[2 * pr][1], bf[2 * pr + 1][0], bf[2 * pr + 1][1],
                      bB + (uint32_t)pr * (16 * SBH) + kB);
#pragma unroll
            for (int mi = 0; mi < 4; mi++)
#pragma unroll
                for (int ni = 0; ni < 8; ni++)
                    mma_f16(acc[mi][ni], af[mi], bf[ni]);
        }
        __syncthreads();
    }

    __half* C = Cg + (size_t)z * sC;
#pragma unroll
    for (int mi = 0; mi < 4; mi++) {
#pragma unroll
        for (int ni = 0; ni < 8; ni++) {
            const int row0 = m0 + wm + mi * 16 + (lane >> 2);
            const int col  = n0 + wn + ni * 8 + (lane & 3) * 2;
#pragma unroll
            for (int h = 0; h < 2; ++h) {
                const int row = row0 + h * 8;
                *(__half2*)(C + (size_t)row * N + col) =
                    __floats2half2_rn(acc[mi][ni][2 * h], acc[mi][ni][2 * h + 1]);
            }
        }
    }
}

// ---------------- launch ----------------
extern "C" void kernel_launch(void* const* d_in, const int* in_sizes, int n_in,
                              void* d_out, int out_size)
{
    const float* keys    = (const float*)d_in[0];   // [16, 2048, 512]
    const float* queries = (const float*)d_in[1];   // [16, 1024, 512]
    const float* values  = (const float*)d_in[2];   // [16, 2048, 512]
    const int*   mask    = (const int*)  d_in[3];   // [16, 1024, 2048]
    const float* W       = (const float*)d_in[4];   // [256, 512]
    const float* bias    = (const float*)d_in[5];   // [256]
    float* out = (float*)d_out;                     // [16, 1024, 256]

    const int B = 16, NQ = 1024, NK = 2048, D = 512, V = 512, O = 256;
    const int BH = B / 2;                           // z-split half
    const float scale = 1.0f / sqrtf(512.0f);       // KQ = 512

    __half *S, *Vt;
    float* RS;
    cudaGetSymbolAddress((void**)&S,  g_S);
    cudaGetSymbolAddress((void**)&Vt, g_Vt);
    cudaGetSymbolAddress((void**)&RS, g_rsum);

    cudaFuncSetAttribute(gemm_a32, cudaFuncAttributeMaxDynamicSharedMemorySize, SMEM_DB);
    cudaFuncSetAttribute(gemm_k1,  cudaFuncAttributeMaxDynamicSharedMemorySize, SMEM_DB);
    cudaFuncSetAttribute(gemm_h16, cudaFuncAttributeMaxDynamicSharedMemorySize, SMEM_DB);

    // Strides
    const long long stQ = (long long)NQ * D;
    const long long stK = (long long)NK * D;
    const long long stS = (long long)NQ * NK;
    const long long stV = (long long)NK * V;
    const long long stT = (long long)O * NK;
    const long long stO = (long long)NQ * O;

    // ONE side stream only (2-branch graph — same width as the R14 graph that
    // passed the teardown check; 3 branches tripped the 2MB upload-pool guard).
    // Host-side resources; intentionally not destroyed (destroying mid-capture
    // would invalidate the graph; kernel_launch runs only twice).
    cudaStream_t s2;
    cudaStreamCreateWithFlags(&s2, cudaStreamNonBlocking);
    cudaEvent_t eFork, eK0, e1a, e3a;
    cudaEventCreateWithFlags(&eFork, cudaEventDisableTiming);
    cudaEventCreateWithFlags(&eK0,   cudaEventDisableTiming);
    cudaEventCreateWithFlags(&e1a,   cudaEventDisableTiming);
    cudaEventCreateWithFlags(&e3a,   cudaEventDisableTiming);

    // ---- fork: K0 (Vt) on s2 ----
    cudaEventRecord(eFork, 0);
    cudaStreamWaitEvent(s2, eFork, 0);
    gemm_a32<<<dim3(NK / BN, O / BM, B), 128, SMEM_DB, s2>>>(
        W, values, Vt, NK, V, 0LL, stV, stT);
    cudaEventRecord(eK0, s2);

    // ---- main: zero row sums, K1 first half (z 0..7) ----
    zero_rs<<<16, 256>>>((float4*)RS);
    gemm_k1<<<dim3(NK / BN, NQ / BM, BH), 128, SMEM_DB>>>(
        queries, keys, S, NK, D, stQ, stK, stS,
        mask, stS, RS, scale);
    cudaEventRecord(e1a, 0);

    // ---- main: K1 second half (z 8..15) ----
    gemm_k1<<<dim3(NK / BN, NQ / BM, BH), 128, SMEM_DB>>>(
        queries + BH * stQ, keys + BH * stK, S + BH * stS, NK, D,
        stQ, stK, stS,
        mask + BH * stS, stS, RS + BH * 1024, scale);

    // ---- s2 (after K0 in program order): K3 first half overlaps K1b ----
    cudaStreamWaitEvent(s2, e1a, 0);
    gemm_h16<<<dim3(O / BN, NQ / BM, BH), 128, SMEM_DB, s2>>>(
        S, Vt, out, O, NK, stS, stT, stO, bias, RS);
    cudaEventRecord(e3a, s2);

    // ---- main: K3 second half (after K1b in stream order; needs K0 too) ----
    cudaStreamWaitEvent(0, eK0, 0);
    gemm_h16<<<dim3(O / BN, NQ / BM, BH), 128, SMEM_DB>>>(
        S + BH * stS, Vt + BH * stT, out + BH * stO, O, NK,
        stS, stT, stO, bias, RS + BH * 1024);

    // join s2 back into the origin stream before capture ends
    cudaStreamWaitEvent(0, e3a, 0);
}

// round 17
// speedup vs baseline: 1.0751x; 1.0751x over previous
#include <cuda_runtime.h>
#include <cuda_fp16.h>
#include <stdint.h>

// ---------------- scratch (alloc-free: __device__ globals) ----------------
__device__ __half g_S [16u * 1024u * 2048u];   // exp(logits), unnormalized  [B,NQ,NK] fp16
__device__ __half g_Vt[16u * 256u  * 2048u];   // V'^T = W @ V^T  [B,O,NK]   fp16
__device__ float  g_rsum[16u * 1024u];         // per-row sum of exp(logits)

// ---------------- helpers ----------------
__device__ __forceinline__ uint32_t smem_u32(const void* p) {
    uint32_t a;
    asm("{ .reg .u64 t; cvta.to.shared.u64 t, %1; cvt.u32.u64 %0, t; }" : "=r"(a) : "l"(p));
    return a;
}
__device__ __forceinline__ uint32_t f16x2(float lo, float hi) {
    uint32_t u;
    asm("cvt.rn.f16x2.f32 %0, %1, %2;" : "=r"(u) : "f"(hi), "f"(lo));
    return u;
}
__device__ __forceinline__ void mma_f16(float c[4], const uint32_t a[4], const uint32_t b[2]) {
    asm volatile(
        "mma.sync.aligned.m16n8k16.row.col.f32.f16.f16.f32 "
        "{%0,%1,%2,%3}, {%4,%5,%6,%7}, {%8,%9}, {%0,%1,%2,%3};"
        : "+f"(c[0]), "+f"(c[1]), "+f"(c[2]), "+f"(c[3])
        : "r"(a[0]), "r"(a[1]), "r"(a[2]), "r"(a[3]), "r"(b[0]), "r"(b[1]));
}
__device__ __forceinline__ void ldsm4(uint32_t& r0, uint32_t& r1, uint32_t& r2, uint32_t& r3,
                                      uint32_t addr) {
    asm volatile("ldmatrix.sync.aligned.m8n8.x4.shared.b16 {%0,%1,%2,%3}, [%4];"
                 : "=r"(r0), "=r"(r1), "=r"(r2), "=r"(r3) : "r"(addr));
}
__device__ __forceinline__ void sts64(uint32_t a, uint32_t x, uint32_t y) {
    asm volatile("st.shared.v2.b32 [%0], {%1,%2};" :: "r"(a), "r"(x), "r"(y) : "memory");
}
__device__ __forceinline__ void sts128(uint32_t a, uint4 v) {
    asm volatile("st.shared.v4.b32 [%0], {%1,%2,%3,%4};"
                 :: "r"(a), "r"(v.x), "r"(v.y), "r"(v.z), "r"(v.w) : "memory");
}

// ---------------- tiling ----------------
// CTA tile 128x128x32, 4 warps as 2(M) x 2(N), warp tile 64x64. 128 threads.
// Two CTAs/SM. fp16 smem rows: 64B data, stride 80B (conflict-free ldmatrix).
constexpr int BM = 128, BN = 128, BK = 32;
constexpr int SBH   = 80;                   // bytes per smem row
constexpr int A_B   = BM * SBH;             // 10240
constexpr int STG_B = (BM + BN) * SBH;      // 20480 per stage
constexpr int SMEM_DB = 2 * STG_B;          // 40960 (double-buffered)

// ===================== zero row_sum =====================
__global__ __launch_bounds__(256)
void zero_rs(float4* __restrict__ rs4)
{
    rs4[blockIdx.x * 256 + threadIdx.x] = make_float4(0.f, 0.f, 0.f, 0.f);
}

// ===================== K1: fp32 inputs (in-kernel cvt), fused epilogue =====
// P[z][m][n] = exp(scale * sum_k Q[z][m][k]*Kk[z][n][k])  (mask==0 -> 0), fp16.
// Row sums of P accumulate into rsum via atomics.
__global__ __launch_bounds__(128, 2)
void gemm_k1(const float* __restrict__ Ag, const float* __restrict__ Bg,
             __half* __restrict__ Cg, int N, int K,
             long long sA, long long sB, long long sC,
             const int* __restrict__ maskg, long long sMask,
             float* __restrict__ rsum, float scale)
{
    extern __shared__ char smem[];

    const int tid  = threadIdx.x;
    const int lane = tid & 31;
    const int warp = tid >> 5;
    const int wm = (warp & 1) * 64;
    const int wn = (warp >> 1) * 64;
    const int z  = blockIdx.z;
    const int m0 = blockIdx.y * BM;
    const int n0 = blockIdx.x * BN;

    const float* A = Ag + (size_t)z * sA;
    const float* B = Bg + (size_t)z * sB;

    const uint32_t sbase = smem_u32(smem);
    const uint32_t aRowB = (uint32_t)(wm + (lane & 15)) * SBH + (uint32_t)(lane >> 4) * 16;
    const uint32_t bRowB = (uint32_t)(wn + (lane & 7) + ((lane >> 4) << 3)) * SBH
                         + (uint32_t)((lane >> 3) & 1) * 16;
    const int KT = K / BK;

    float4 ra[8], rb[8];
    auto load_regs = [&](int c) {
        const int koff = c * BK;
#pragma unroll
        for (int i = 0; i < 8; i++) {
            int f = tid + 128 * i, r = f >> 3, q = (f & 7) * 4;
            ra[i] = *(const float4*)(A + (size_t)(m0 + r) * K + koff + q);
        }
#pragma unroll
        for (int i = 0; i < 8; i++) {
            int f = tid + 128 * i, r = f >> 3, q = (f & 7) * 4;
            rb[i] = *(const float4*)(B + (size_t)(n0 + r) * K + koff + q);
        }
    };
    auto store_stage = [&](int s) {
        const uint32_t st = sbase + (uint32_t)s * STG_B;
#pragma unroll
        for (int i = 0; i < 8; i++) {
            int f = tid + 128 * i, r = f >> 3, q = (f & 7) * 4;
            sts64(st + (uint32_t)r * SBH + (uint32_t)q * 2,
                  f16x2(ra[i].x, ra[i].y), f16x2(ra[i].z, ra[i].w));
        }
#pragma unroll
        for (int i = 0; i < 8; i++) {
            int f = tid + 128 * i, r = f >> 3, q = (f & 7) * 4;
            sts64(st + (uint32_t)A_B + (uint32_t)r * SBH + (uint32_t)q * 2,
                  f16x2(rb[i].x, rb[i].y), f16x2(rb[i].z, rb[i].w));
        }
    };

    float acc[4][8][4];
#pragma unroll
    for (int i = 0; i < 4; i++)
#pragma unroll
        for (int j = 0; j < 8; j++)
#pragma unroll
            for (int r = 0; r < 4; r++) acc[i][j][r] = 0.0f;

    load_regs(0);
    store_stage(0);
    __syncthreads();
    if (KT > 1) load_regs(1);

    for (int kb = 0; kb < KT; ++kb) {
        const int cur = kb & 1;
        if (kb + 1 < KT) store_stage(cur ^ 1);
        if (kb + 2 < KT) load_regs(kb + 2);

        const uint32_t curBase = sbase + (uint32_t)cur * STG_B;
        const uint32_t aB = curBase + aRowB;
        const uint32_t bB = curBase + (uint32_t)A_B + bRowB;

#pragma unroll
        for (int ks = 0; ks < 2; ++ks) {
            const uint32_t kB = (uint32_t)ks * 32;
            uint32_t af[4][4], bf[8][2];
#pragma unroll
            for (int mi = 0; mi < 4; mi++)
                ldsm4(af[mi][0], af[mi][1], af[mi][2], af[mi][3],
                      aB + (uint32_t)mi * (16 * SBH) + kB);
#pragma unroll
            for (int pr = 0; pr < 4; pr++)
                ldsm4(bf[2 * pr][0], bf[2 * pr][1], bf[2 * pr + 1][0], bf[2 * pr + 1][1],
                      bB + (uint32_t)pr * (16 * SBH) + kB);
#pragma unroll
            for (int mi = 0; mi < 4; mi++)
#pragma unroll
                for (int ni = 0; ni < 8; ni++)
                    mma_f16(acc[mi][ni], af[mi], bf[ni]);
        }
        __syncthreads();
    }

    // ---- fused epilogue: exp + mask -> store P, reduce row partial sums ----
    __half* C = Cg + (size_t)z * sC;
    const int* Mk = maskg + (size_t)z * sMask;
    float* RS = rsum + (size_t)z * 1024;

#pragma unroll
    for (int mi = 0; mi < 4; mi++) {
        const int row0 = m0 + wm + mi * 16 + (lane >> 2);
        float psum[2] = {0.0f, 0.0f};
#pragma unroll
        for (int ni = 0; ni < 8; ni++) {
            const int col = n0 + wn + ni * 8 + (lane & 3) * 2;
#pragma unroll
            for (int h = 0; h < 2; ++h) {
                const int row = row0 + h * 8;
                int2 mk = *(const int2*)(Mk + (size_t)row * N + col);
                float v0 = mk.x ? __expf(acc[mi][ni][2 * h] * scale)     : 0.0f;
                float v1 = mk.y ? __expf(acc[mi][ni][2 * h + 1] * scale) : 0.0f;
                psum[h] += v0 + v1;
                *(__half2*)(C + (size_t)row * N + col) = __floats2half2_rn(v0, v1);
            }
        }
#pragma unroll
        for (int h = 0; h < 2; ++h) {
            float s = psum[h];
            s += __shfl_xor_sync(0xffffffffu, s, 1);
            s += __shfl_xor_sync(0xffffffffu, s, 2);
            if ((lane & 3) == 0) atomicAdd(RS + row0 + h * 8, s);
        }
    }
}

// ===================== K3: fp16 in -> fp32 out, scale by 1/rowsum + bias ===
__global__ __launch_bounds__(128, 2)
void gemm_h16(const __half* __restrict__ Ag, const __half* __restrict__ Bg,
              float* __restrict__ Cg, int N, int K,
              long long sA, long long sB, long long sC,
              const float* __restrict__ bias, const float* __restrict__ rsum)
{
    extern __shared__ char smem[];

    const int tid  = threadIdx.x;
    const int lane = tid & 31;
    const int warp = tid >> 5;
    const int wm = (warp & 1) * 64;
    const int wn = (warp >> 1) * 64;
    const int z  = blockIdx.z;
    const int m0 = blockIdx.y * BM;
    const int n0 = blockIdx.x * BN;

    const __half* A = Ag + (size_t)z * sA;
    const __half* B = Bg + (size_t)z * sB;

    const uint32_t sbase = smem_u32(smem);
    const uint32_t aRowB = (uint32_t)(wm + (lane & 15)) * SBH + (uint32_t)(lane >> 4) * 16;
    const uint32_t bRowB = (uint32_t)(wn + (lane & 7) + ((lane >> 4) << 3)) * SBH
                         + (uint32_t)((lane >> 3) & 1) * 16;
    const int KT = K / BK;

    uint4 ra[4], rb[4];
    auto load_regs = [&](int c) {
        const int koff = c * BK;
#pragma unroll
        for (int i = 0; i < 4; i++) {
            int f = tid + 128 * i, r = f >> 2, sg = f & 3;
            ra[i] = *(const uint4*)(A + (size_t)(m0 + r) * K + koff + sg * 8);
        }
#pragma unroll
        for (int i = 0; i < 4; i++) {
            int f = tid + 128 * i, r = f >> 2, sg = f & 3;
            rb[i] = *(const uint4*)(B + (size_t)(n0 + r) * K + koff + sg * 8);
        }
    };
    auto store_stage = [&](int s) {
        const uint32_t st = sbase + (uint32_t)s * STG_B;
#pragma unroll
        for (int i = 0; i < 4; i++) {
            int f = tid + 128 * i, r = f >> 2, sg = f & 3;
            sts128(st + (uint32_t)r * SBH + (uint32_t)sg * 16, ra[i]);
        }
#pragma unroll
        for (int i = 0; i < 4; i++) {
            int f = tid + 128 * i, r = f >> 2, sg = f & 3;
            sts128(st + (uint32_t)A_B + (uint32_t)r * SBH + (uint32_t)sg * 16, rb[i]);
        }
    };

    float acc[4][8][4];
#pragma unroll
    for (int i = 0; i < 4; i++)
#pragma unroll
        for (int j = 0; j < 8; j++)
#pragma unroll
            for (int r = 0; r < 4; r++) acc[i][j][r] = 0.0f;

    load_regs(0);
    store_stage(0);
    __syncthreads();
    if (KT > 1) load_regs(1);

    for (int kb = 0; kb < KT; ++kb) {
        const int cur = kb & 1;
        if (kb + 1 < KT) store_stage(cur ^ 1);
        if (kb + 2 < KT) load_regs(kb + 2);

        const uint32_t curBase = sbase + (uint32_t)cur * STG_B;
        const uint32_t aB = curBase + aRowB;
        const uint32_t bB = curBase + (uint32_t)A_B + bRowB;

#pragma unroll
        for (int ks = 0; ks < 2; ++ks) {
            const uint32_t kB = (uint32_t)ks * 32;
            uint32_t af[4][4], bf[8][2];
#pragma unroll
            for (int mi = 0; mi < 4; mi++)
                ldsm4(af[mi][0], af[mi][1], af[mi][2], af[mi][3],
                      aB + (uint32_t)mi * (16 * SBH) + kB);
#pragma unroll
            for (int pr = 0; pr < 4; pr++)
                ldsm4(bf[2 * pr][0], bf[2 * pr][1], bf[2 * pr + 1][0], bf[2 * pr + 1][1],
                      bB + (uint32_t)pr * (16 * SBH) + kB);
#pragma unroll
            for (int mi = 0; mi < 4; mi++)
#pragma unroll
                for (int ni = 0; ni < 8; ni++)
                    mma_f16(acc[mi][ni], af[mi], bf[ni]);
        }
        __syncthreads();
    }

    float* C = Cg + (size_t)z * sC;
    const float* RS = rsum + (size_t)z * 1024;
#pragma unroll
    for (int mi = 0; mi < 4; mi++) {
        const int row0 = m0 + wm + mi * 16 + (lane >> 2);
        const float inv0 = 1.0f / RS[row0];
        const float inv1 = 1.0f / RS[row0 + 8];
#pragma unroll
        for (int ni = 0; ni < 8; ni++) {
            const int col = n0 + wn + ni * 8 + (lane & 3) * 2;
            const float b0 = bias[col], b1 = bias[col + 1];
            float2 o;
            o.x = acc[mi][ni][0] * inv0 + b0;
            o.y = acc[mi][ni][1] * inv0 + b1;
            *(float2*)(C + (size_t)row0 * N + col) = o;
            o.x = acc[mi][ni][2] * inv1 + b0;
            o.y = acc[mi][ni][3] * inv1 + b1;
            *(float2*)(C + (size_t)(row0 + 8) * N + col) = o;
        }
    }
}

// ===================== K0: fp32 inputs -> fp16 out =========================
__global__ __launch_bounds__(128, 2)
void gemm_a32(const float* __restrict__ Ag, const float* __restrict__ Bg,
              __half* __restrict__ Cg, int N, int K,
              long long sA, long long sB, long long sC)
{
    extern __shared__ char smem[];

    const int tid  = threadIdx.x;
    const int lane = tid & 31;
    const int warp = tid >> 5;
    const int wm = (warp & 1) * 64;
    const int wn = (warp >> 1) * 64;
    const int z  = blockIdx.z;
    const int m0 = blockIdx.y * BM;
    const int n0 = blockIdx.x * BN;

    const float* A = Ag + (size_t)z * sA;
    const float* B = Bg + (size_t)z * sB;

    const uint32_t sbase = smem_u32(smem);
    const uint32_t aRowB = (uint32_t)(wm + (lane & 15)) * SBH + (uint32_t)(lane >> 4) * 16;
    const uint32_t bRowB = (uint32_t)(wn + (lane & 7) + ((lane >> 4) << 3)) * SBH
                         + (uint32_t)((lane >> 3) & 1) * 16;
    const int KT = K / BK;

    float4 ra[8], rb[8];
    auto load_regs = [&](int c) {
        const int koff = c * BK;
#pragma unroll
        for (int i = 0; i < 8; i++) {
            int f = tid + 128 * i, r = f >> 3, q = (f & 7) * 4;
            ra[i] = *(const float4*)(A + (size_t)(m0 + r) * K + koff + q);
        }
#pragma unroll
        for (int i = 0; i < 8; i++) {
            int f = tid + 128 * i, r = f >> 3, q = (f & 7) * 4;
            rb[i] = *(const float4*)(B + (size_t)(n0 + r) * K + koff + q);
        }
    };
    auto store_stage = [&](int s) {
        const uint32_t st = sbase + (uint32_t)s * STG_B;
#pragma unroll
        for (int i = 0; i < 8; i++) {
            int f = tid + 128 * i, r = f >> 3, q = (f & 7) * 4;
            sts64(st + (uint32_t)r * SBH + (uint32_t)q * 2,
                  f16x2(ra[i].x, ra[i].y), f16x2(ra[i].z, ra[i].w));
        }
#pragma unroll
        for (int i = 0; i < 8; i++) {
            int f = tid + 128 * i, r = f >> 3, q = (f & 7) * 4;
            sts64(st + (uint32_t)A_B + (uint32_t)r * SBH + (uint32_t)q * 2,
                  f16x2(rb[i].x, rb[i].y), f16x2(rb[i].z, rb[i].w));
        }
    };

    float acc[4][8][4];
#pragma unroll
    for (int i = 0; i < 4; i++)
#pragma unroll
        for (int j = 0; j < 8; j++)
#pragma unroll
            for (int r = 0; r < 4; r++) acc[i][j][r] = 0.0f;

    load_regs(0);
    store_stage(0);
    __syncthreads();
    if (KT > 1) load_regs(1);

    for (int kb = 0; kb < KT; ++kb) {
        const int cur = kb & 1;
        if (kb + 1 < KT) store_stage(cur ^ 1);
        if (kb + 2 < KT) load_regs(kb + 2);

        const uint32_t curBase = sbase + (uint32_t)cur * STG_B;
        const uint32_t aB = curBase + aRowB;
        const uint32_t bB = curBase + (uint32_t)A_B + bRowB;

#pragma unroll
        for (int ks = 0; ks < 2; ++ks) {
            const uint32_t kB = (uint32_t)ks * 32;
            uint32_t af[4][4], bf[8][2];
#pragma unroll
            for (int mi = 0; mi < 4; mi++)
                ldsm4(af[mi][0], af[mi][1], af[mi][2], af[mi][3],
                      aB + (uint32_t)mi * (16 * SBH) + kB);
#pragma unroll
            for (int pr = 0; pr < 4; pr++)
                ldsm4(bf[2 * pr][0], bf[2 * pr][1], bf[2 * pr + 1][0], bf[2 * pr + 1][1],
                      bB + (uint32_t)pr * (16 * SBH) + kB);
#pragma unroll
            for (int mi = 0; mi < 4; mi++)
#pragma unroll
                for (int ni = 0; ni < 8; ni++)
                    mma_f16(acc[mi][ni], af[mi], bf[ni]);
        }
        __syncthreads();
    }

    __half* C = Cg + (size_t)z * sC;
#pragma unroll
    for (int mi = 0; mi < 4; mi++) {
#pragma unroll
        for (int ni = 0; ni < 8; ni++) {
            const int row0 = m0 + wm + mi * 16 + (lane >> 2);
            const int col  = n0 + wn + ni * 8 + (lane & 3) * 2;
#pragma unroll
            for (int h = 0; h < 2; ++h) {
                const int row = row0 + h * 8;
                *(__half2*)(C + (size_t)row * N + col) =
                    __floats2half2_rn(acc[mi][ni][2 * h], acc[mi][ni][2 * h + 1]);
            }
        }
    }
}

// ---------------- launch (R14 topology: serial main path, K0 forked) -------
extern "C" void kernel_launch(void* const* d_in, const int* in_sizes, int n_in,
                              void* d_out, int out_size)
{
    const float* keys    = (const float*)d_in[0];   // [16, 2048, 512]
    const float* queries = (const float*)d_in[1];   // [16, 1024, 512]
    const float* values  = (const float*)d_in[2];   // [16, 2048, 512]
    const int*   mask    = (const int*)  d_in[3];   // [16, 1024, 2048]
    const float* W       = (const float*)d_in[4];   // [256, 512]
    const float* bias    = (const float*)d_in[5];   // [256]
    float* out = (float*)d_out;                     // [16, 1024, 256]

    const int B = 16, NQ = 1024, NK = 2048, D = 512, V = 512, O = 256;
    const float scale = 1.0f / sqrtf(512.0f);       // KQ = 512

    __half *S, *Vt;
    float* RS;
    cudaGetSymbolAddress((void**)&S,  g_S);
    cudaGetSymbolAddress((void**)&Vt, g_Vt);
    cudaGetSymbolAddress((void**)&RS, g_rsum);

    cudaFuncSetAttribute(gemm_a32, cudaFuncAttributeMaxDynamicSharedMemorySize, SMEM_DB);
    cudaFuncSetAttribute(gemm_k1,  cudaFuncAttributeMaxDynamicSharedMemorySize, SMEM_DB);
    cudaFuncSetAttribute(gemm_h16, cudaFuncAttributeMaxDynamicSharedMemorySize, SMEM_DB);

    // Host-side stream/events; intentionally not destroyed (kernel_launch runs
    // only for correctness + capture; destroying mid-capture invalidates graph).
    cudaStream_t s2;
    cudaStreamCreateWithFlags(&s2, cudaStreamNonBlocking);
    cudaEvent_t eFork, eJoin;
    cudaEventCreateWithFlags(&eFork, cudaEventDisableTiming);
    cudaEventCreateWithFlags(&eJoin, cudaEventDisableTiming);

    // Main stream: zero row sums first (tiny), fork point after it so the
    // side branch's wait also covers it.
    zero_rs<<<16, 256>>>((float4*)RS);
    cudaEventRecord(eFork, 0);
    cudaStreamWaitEvent(s2, eFork, 0);

    // K0 on s2: Vt[b][o][n] = sum_v W[o][v] * values[b][n][v]  (fp32 in, fp16 out)
    gemm_a32<<<dim3(NK / BN, O / BM, B), 128, SMEM_DB, s2>>>(
        W, values, Vt, NK, V,
        0LL, (long long)NK * V, (long long)O * NK);
    cudaEventRecord(eJoin, s2);

    // K1: P = exp(scale * Q @ K^T) (masked -> 0), fp32 inputs converted
    // in-kernel, row sums -> RS
    gemm_k1<<<dim3(NK / BN, NQ / BM, B), 128, SMEM_DB>>>(
        queries, keys, S, NK, D,
        (long long)NQ * D, (long long)NK * D, (long long)NQ * NK,
        mask, (long long)NQ * NK, RS, scale);

    // Join: K3 needs both K1 (stream 0) and K0 (s2).
    cudaStreamWaitEvent(0, eJoin, 0);

    // K3: out = (P @ Vt^T) / rowsum + bias   (fp16 in, fp32 out)
    gemm_h16<<<dim3(O / BN, NQ / BM, B), 128, SMEM_DB>>>(
        S, Vt, out, O, NK,
        (long long)NQ * NK, (long long)O * NK, (long long)NQ * O,
        bias, RS);
}